// round 5
// baseline (speedup 1.0000x reference)
#include <cuda_runtime.h>
#include <cstdint>

#define T_TOK 1024
#define HDIM  2048
#define NEXP  16
#define IDIM  1408
#define SI    2816
#define TOPK  4

typedef unsigned long long ull;
typedef unsigned int u32;

// ---------------- scratch (device globals; no allocation allowed) ----------------
__device__ int   g_cnt[NEXP];
__device__ int   g_tok[NEXP * T_TOK];
__device__ float g_tw [NEXP * T_TOK];
__device__ int   g_tid4[T_TOK * TOPK];
__device__ float g_twk4[T_TOK * TOPK];
__device__ float g_act [(size_t)NEXP * T_TOK * IDIM];   // routed activations (slot-major)
__device__ float g_acts[(size_t)T_TOK * SI];            // shared activations

// ---------------- helpers ----------------
__device__ __forceinline__ float to_tf32(float f) {
    u32 u;
    asm("cvt.rna.tf32.f32 %0, %1;" : "=r"(u) : "f"(f));
    return __uint_as_float(u);
}
__device__ __forceinline__ float4 tf32_4(float4 v) {
    v.x = to_tf32(v.x); v.y = to_tf32(v.y); v.z = to_tf32(v.z); v.w = to_tf32(v.w);
    return v;
}
__device__ __forceinline__ void mma8(float* d, const u32* a, const u32* b) {
    asm volatile(
        "mma.sync.aligned.m16n8k8.row.col.f32.tf32.tf32.f32 "
        "{%0,%1,%2,%3}, {%4,%5,%6,%7}, {%8,%9}, {%0,%1,%2,%3};"
        : "+f"(d[0]), "+f"(d[1]), "+f"(d[2]), "+f"(d[3])
        : "r"(a[0]), "r"(a[1]), "r"(a[2]), "r"(a[3]), "r"(b[0]), "r"(b[1]));
}
__device__ __forceinline__ float silu_f(float g) { return g / (1.f + expf(-g)); }

// ---------------- router (exact fp32) ----------------
__global__ void router_kernel(const float* __restrict__ x,
                              const float* __restrict__ gw,
                              const float* __restrict__ bias,
                              int* __restrict__ tid4, float* __restrict__ twk4)
{
    int t = blockIdx.x;
    int tid = threadIdx.x;            // 128 threads: 16 experts x 8 lanes
    int e = tid >> 3, r = tid & 7;
    const float4* x4 = reinterpret_cast<const float4*>(x + (size_t)t * HDIM);
    const float4* w4 = reinterpret_cast<const float4*>(gw + (size_t)e * HDIM);
    float s = 0.f;
    #pragma unroll 4
    for (int j = r; j < HDIM / 4; j += 8) {
        float4 a = x4[j], b = w4[j];
        s += a.x * b.x + a.y * b.y + a.z * b.z + a.w * b.w;
    }
    #pragma unroll
    for (int o = 4; o > 0; o >>= 1) s += __shfl_down_sync(0xffffffffu, s, o, 8);
    __shared__ float logit[NEXP];
    if (r == 0) logit[e] = s;
    __syncthreads();
    if (tid == 0) {
        float sc[NEXP], sb[NEXP];
        #pragma unroll
        for (int i = 0; i < NEXP; i++) {
            sc[i] = 1.f / (1.f + expf(-logit[i]));
            sb[i] = sc[i] + bias[i];
        }
        float gsc[4];
        #pragma unroll
        for (int g = 0; g < 4; g++) {
            const float* p = sb + g * 4;
            float m1 = p[0]; int i1 = 0;
            for (int i = 1; i < 4; i++) if (p[i] > m1) { m1 = p[i]; i1 = i; }
            float m2 = -1e30f;
            for (int i = 0; i < 4; i++) if (i != i1 && p[i] > m2) m2 = p[i];
            gsc[g] = m1 + m2;
        }
        int g1 = 0; for (int g = 1; g < 4; g++) if (gsc[g] > gsc[g1]) g1 = g;
        int g2 = (g1 == 0) ? 1 : 0;
        for (int g = 0; g < 4; g++) if (g != g1 && gsc[g] > gsc[g2]) g2 = g;
        bool allow[NEXP];
        for (int i = 0; i < NEXP; i++) { int g = i >> 2; allow[i] = (g == g1 || g == g2); }
        int ids[TOPK]; float wsum = 0.f;
        for (int k = 0; k < TOPK; k++) {
            int best = 0; float bv = -1e30f;
            for (int i = 0; i < NEXP; i++)
                if (allow[i] && sb[i] > bv) { bv = sb[i]; best = i; }
            allow[best] = false;
            ids[k] = best;
            wsum += sc[best];
        }
        for (int k = 0; k < TOPK; k++) {
            tid4[t * TOPK + k] = ids[k];
            twk4[t * TOPK + k] = sc[ids[k]] / wsum;
        }
    }
}

// ---------------- deterministic per-expert token lists ----------------
__global__ void build_lists(const int* __restrict__ tid4, const float* __restrict__ twk4,
                            int* __restrict__ cnt, int* __restrict__ tok, float* __restrict__ tw)
{
    int e = threadIdx.x;
    if (e >= NEXP) return;
    int c = 0;
    for (int t = 0; t < T_TOK; t++) {
        int4  id = reinterpret_cast<const int4*>(tid4)[t];
        float4 w = reinterpret_cast<const float4*>(twk4)[t];
        if (id.x == e) { tok[e * T_TOK + c] = t; tw[e * T_TOK + c] = w.x * 2.5f; c++; }
        if (id.y == e) { tok[e * T_TOK + c] = t; tw[e * T_TOK + c] = w.y * 2.5f; c++; }
        if (id.z == e) { tok[e * T_TOK + c] = t; tw[e * T_TOK + c] = w.z * 2.5f; c++; }
        if (id.w == e) { tok[e * T_TOK + c] = t; tw[e * T_TOK + c] = w.w * 2.5f; c++; }
    }
    cnt[e] = c;
}

// =====================================================================
// gate_up GEMM via mma.sync tf32, DOUBLE-BUFFERED (1 barrier / k-iter)
// CTA tile 128m x (128 g-cols + 128 u-cols); 8 warps = 2m x 4n;
// warp tile 64m x (32g + 32u). act = silu(g)*u*w
// =====================================================================
#define SA 36
#define SB 136
#define GU_BUF (128 * SA + 2 * 32 * SB)
#define GU_DYN ((2 * GU_BUF + 256) * 4)
__global__ void __launch_bounds__(256)
gu_mma(const float* __restrict__ X, const float* __restrict__ W,
       float* __restrict__ ACT,
       const int* __restrict__ tok, const float* __restrict__ tw,
       const int* __restrict__ cnt, int Iw, int K)
{
    extern __shared__ float smf[];
    // buffer b: As at smf + b*GU_BUF, Bg after As, Bu after Bg
    int*   tokSm = (int*)(smf + 2 * GU_BUF);   // [128]
    float* twSm  = (float*)(tokSm + 128);      // [128]

    int e = blockIdx.z;
    int cn = cnt ? cnt[e] : T_TOK;
    int m0 = blockIdx.y * 128;
    if (m0 >= cn) return;
    int n0 = blockIdx.x * 128;
    int ldW = 2 * Iw;
    const float* We = W + (size_t)e * K * ldW;
    float* actE = ACT + (size_t)e * T_TOK * Iw;

    int tid = threadIdx.x;
    if (tid < 128) {
        int s = m0 + tid; int a; float wv;
        if (tok) {
            const int* tokE = tok + e * T_TOK;
            const float* twE = tw + e * T_TOK;
            if (s < cn) { a = tokE[s]; wv = twE[s]; } else { a = 0; wv = 0.f; }
        } else { a = s; wv = 1.f; }
        tokSm[tid] = a; twSm[tid] = wv;
    }
    __syncthreads();

    // staging mapping: A row per thread-pair; B 4-float interleaved quads
    int arow = tid >> 1, kh = (tid & 1) * 16;
    const float* aP = X + (size_t)tokSm[arow] * K + kh;
    int bk = tid >> 3, bc = (tid & 7) * 4;
    const float* gP = We + (size_t)bk * ldW + n0 + bc;
    const float* uP = gP + Iw;

    // warp mapping: 2m x 4n
    int w = tid >> 5, lane = tid & 31;
    int g = lane >> 2, t = lane & 3;
    int wm = (w & 1) * 64, wn = (w >> 1) * 32;

    float ag[4][4][4], au[4][4][4];
    #pragma unroll
    for (int i = 0; i < 4; i++)
        #pragma unroll
        for (int j = 0; j < 4; j++)
            #pragma unroll
            for (int q = 0; q < 4; q++) { ag[i][j][q] = 0.f; au[i][j][q] = 0.f; }

    float4 pa[4], pg[4], pu[4];
    const int NK = K / 32;

    // prologue: tile 0 -> regs -> buf0; tile 1 -> regs
    #pragma unroll
    for (int i = 0; i < 4; i++) {
        pa[i] = *(const float4*)(aP + 4 * i);
        pg[i] = *(const float4*)(gP + 32 * i);
        pu[i] = *(const float4*)(uP + 32 * i);
    }
    {
        float* As = smf; float* Bg = As + 128 * SA; float* Bu = Bg + 32 * SB;
        #pragma unroll
        for (int i = 0; i < 4; i++) {
            *(float4*)&As[arow * SA + kh + 4 * i] = tf32_4(pa[i]);
            *(float4*)&Bg[bk * SB + bc + 32 * i]  = tf32_4(pg[i]);
            *(float4*)&Bu[bk * SB + bc + 32 * i]  = tf32_4(pu[i]);
        }
    }
    if (NK > 1) {
        const float* aN = aP + 32;
        const float* gN = gP + (size_t)32 * ldW;
        const float* uN = gN + Iw;
        #pragma unroll
        for (int i = 0; i < 4; i++) {
            pa[i] = *(const float4*)(aN + 4 * i);
            pg[i] = *(const float4*)(gN + 32 * i);
            pu[i] = *(const float4*)(uN + 32 * i);
        }
    }
    __syncthreads();

    for (int it = 0; it < NK; ++it) {
        int b = it & 1;
        // stage tile it+1 into the other buffer (regs already hold it)
        if (it + 1 < NK) {
            float* As = smf + (1 - b) * GU_BUF;
            float* Bg = As + 128 * SA; float* Bu = Bg + 32 * SB;
            #pragma unroll
            for (int i = 0; i < 4; i++) {
                *(float4*)&As[arow * SA + kh + 4 * i] = tf32_4(pa[i]);
                *(float4*)&Bg[bk * SB + bc + 32 * i]  = tf32_4(pg[i]);
                *(float4*)&Bu[bk * SB + bc + 32 * i]  = tf32_4(pu[i]);
            }
        }
        // issue global loads for tile it+2
        if (it + 2 < NK) {
            const float* aN = aP + (it + 2) * 32;
            const float* gN = gP + (size_t)(it + 2) * 32 * ldW;
            const float* uN = gN + Iw;
            #pragma unroll
            for (int i = 0; i < 4; i++) {
                pa[i] = *(const float4*)(aN + 4 * i);
                pg[i] = *(const float4*)(gN + 32 * i);
                pu[i] = *(const float4*)(uN + 32 * i);
            }
        }
        // MMA on buffer b
        {
            const float* As = smf + b * GU_BUF;
            const float* Bg = As + 128 * SA; const float* Bu = Bg + 32 * SB;
            #pragma unroll
            for (int ks = 0; ks < 4; ++ks) {
                int k0 = ks * 8;
                u32 af[4][4];
                #pragma unroll
                for (int mt = 0; mt < 4; ++mt) {
                    int r = wm + mt * 16 + g;
                    af[mt][0] = __float_as_uint(As[r * SA + k0 + t]);
                    af[mt][1] = __float_as_uint(As[(r + 8) * SA + k0 + t]);
                    af[mt][2] = __float_as_uint(As[r * SA + k0 + t + 4]);
                    af[mt][3] = __float_as_uint(As[(r + 8) * SA + k0 + t + 4]);
                }
                #pragma unroll
                for (int nt = 0; nt < 4; ++nt) {
                    int n = wn + nt * 8 + g;
                    u32 bg2[2] = { __float_as_uint(Bg[(k0 + t) * SB + n]),
                                   __float_as_uint(Bg[(k0 + t + 4) * SB + n]) };
                    u32 bu2[2] = { __float_as_uint(Bu[(k0 + t) * SB + n]),
                                   __float_as_uint(Bu[(k0 + t + 4) * SB + n]) };
                    #pragma unroll
                    for (int mt = 0; mt < 4; ++mt) {
                        mma8(ag[mt][nt], af[mt], bg2);
                        mma8(au[mt][nt], af[mt], bu2);
                    }
                }
            }
        }
        __syncthreads();
    }

    // epilogue: silu(g)*u*w -> act
    #pragma unroll
    for (int mt = 0; mt < 4; ++mt) {
        int l0 = wm + mt * 16 + g;
        int s0 = m0 + l0, s1 = s0 + 8;
        bool v0 = s0 < cn, v1 = s1 < cn;
        float w0 = twSm[l0], w1 = twSm[l0 + 8];
        float* o0 = actE + (size_t)s0 * Iw + n0 + wn;
        float* o1 = actE + (size_t)s1 * Iw + n0 + wn;
        #pragma unroll
        for (int nt = 0; nt < 4; ++nt) {
            int c = nt * 8 + 2 * t;
            if (v0) {
                float2 r;
                r.x = silu_f(ag[mt][nt][0]) * au[mt][nt][0] * w0;
                r.y = silu_f(ag[mt][nt][1]) * au[mt][nt][1] * w0;
                *(float2*)(o0 + c) = r;
            }
            if (v1) {
                float2 r;
                r.x = silu_f(ag[mt][nt][2]) * au[mt][nt][2] * w1;
                r.y = silu_f(ag[mt][nt][3]) * au[mt][nt][3] * w1;
                *(float2*)(o1 + c) = r;
            }
        }
    }
}

// =====================================================================
// down-proj GEMM via mma.sync tf32, DOUBLE-BUFFERED (1 barrier / k-iter)
// CTA tile 128m x 256n; 8 warps = 2m x 4n; warp tile 64m x 64n.
// routed: atomicAdd scatter to out rows; shared: plain store.
// =====================================================================
#define SBD 264
#define DN_BUF (128 * SA + 32 * SBD)
#define DN_DYN ((2 * DN_BUF + 128) * 4)
__global__ void __launch_bounds__(256)
down_mma(const float* __restrict__ A, const float* __restrict__ W,
         float* __restrict__ OUT, const int* __restrict__ tok,
         const int* __restrict__ cnt, int K, int accum)
{
    extern __shared__ float smf[];
    int* tokSm = (int*)(smf + 2 * DN_BUF);  // [128]

    int e = blockIdx.z;
    int cn = cnt ? cnt[e] : T_TOK;
    int m0 = blockIdx.y * 128;
    if (m0 >= cn) return;
    int n0 = blockIdx.x * 256;
    const float* Ae = A + (size_t)e * T_TOK * K;
    const float* Be = W + (size_t)e * K * HDIM;

    int tid = threadIdx.x;
    if (tid < 128) {
        int s = m0 + tid;
        tokSm[tid] = tok ? ((s < cn) ? tok[e * T_TOK + s] : 0) : s;
    }
    __syncthreads();

    int arow = tid >> 1, kh = (tid & 1) * 16;
    const float* aP = Ae + (size_t)(m0 + arow) * K + kh;
    int bk = tid >> 3, bc = (tid & 7) * 4;
    const float* bP = Be + (size_t)bk * HDIM + n0 + bc;

    int w = tid >> 5, lane = tid & 31;
    int g = lane >> 2, t = lane & 3;
    int wm = (w & 1) * 64, wn = (w >> 1) * 64;

    float ac[4][8][4];
    #pragma unroll
    for (int i = 0; i < 4; i++)
        #pragma unroll
        for (int j = 0; j < 8; j++)
            #pragma unroll
            for (int q = 0; q < 4; q++) ac[i][j][q] = 0.f;

    float4 pa[4], pb[8];
    const int NK = K / 32;

    // prologue
    #pragma unroll
    for (int i = 0; i < 4; i++) pa[i] = *(const float4*)(aP + 4 * i);
    #pragma unroll
    for (int i = 0; i < 8; i++) pb[i] = *(const float4*)(bP + 32 * i);
    {
        float* As = smf; float* Bs = As + 128 * SA;
        #pragma unroll
        for (int i = 0; i < 4; i++)
            *(float4*)&As[arow * SA + kh + 4 * i] = tf32_4(pa[i]);
        #pragma unroll
        for (int i = 0; i < 8; i++)
            *(float4*)&Bs[bk * SBD + bc + 32 * i] = tf32_4(pb[i]);
    }
    if (NK > 1) {
        const float* aN = aP + 32;
        const float* bN = bP + (size_t)32 * HDIM;
        #pragma unroll
        for (int i = 0; i < 4; i++) pa[i] = *(const float4*)(aN + 4 * i);
        #pragma unroll
        for (int i = 0; i < 8; i++) pb[i] = *(const float4*)(bN + 32 * i);
    }
    __syncthreads();

    for (int it = 0; it < NK; ++it) {
        int b = it & 1;
        if (it + 1 < NK) {
            float* As = smf + (1 - b) * DN_BUF; float* Bs = As + 128 * SA;
            #pragma unroll
            for (int i = 0; i < 4; i++)
                *(float4*)&As[arow * SA + kh + 4 * i] = tf32_4(pa[i]);
            #pragma unroll
            for (int i = 0; i < 8; i++)
                *(float4*)&Bs[bk * SBD + bc + 32 * i] = tf32_4(pb[i]);
        }
        if (it + 2 < NK) {
            const float* aN = aP + (it + 2) * 32;
            const float* bN = bP + (size_t)(it + 2) * 32 * HDIM;
            #pragma unroll
            for (int i = 0; i < 4; i++) pa[i] = *(const float4*)(aN + 4 * i);
            #pragma unroll
            for (int i = 0; i < 8; i++) pb[i] = *(const float4*)(bN + 32 * i);
        }
        {
            const float* As = smf + b * DN_BUF; const float* Bs = As + 128 * SA;
            #pragma unroll
            for (int ks = 0; ks < 4; ++ks) {
                int k0 = ks * 8;
                u32 af[4][4];
                #pragma unroll
                for (int mt = 0; mt < 4; ++mt) {
                    int r = wm + mt * 16 + g;
                    af[mt][0] = __float_as_uint(As[r * SA + k0 + t]);
                    af[mt][1] = __float_as_uint(As[(r + 8) * SA + k0 + t]);
                    af[mt][2] = __float_as_uint(As[r * SA + k0 + t + 4]);
                    af[mt][3] = __float_as_uint(As[(r + 8) * SA + k0 + t + 4]);
                }
                #pragma unroll
                for (int nt = 0; nt < 8; ++nt) {
                    int n = wn + nt * 8 + g;
                    u32 bf2[2] = { __float_as_uint(Bs[(k0 + t) * SBD + n]),
                                   __float_as_uint(Bs[(k0 + t + 4) * SBD + n]) };
                    #pragma unroll
                    for (int mt = 0; mt < 4; ++mt)
                        mma8(ac[mt][nt], af[mt], bf2);
                }
            }
        }
        __syncthreads();
    }

    #pragma unroll
    for (int mt = 0; mt < 4; ++mt) {
        int l0 = wm + mt * 16 + g;
        int s0 = m0 + l0, s1 = s0 + 8;
        bool v0 = s0 < cn, v1 = s1 < cn;
        float* o0 = OUT + (size_t)tokSm[l0] * HDIM + n0 + wn;
        float* o1 = OUT + (size_t)tokSm[l0 + 8] * HDIM + n0 + wn;
        #pragma unroll
        for (int nt = 0; nt < 8; ++nt) {
            int c = nt * 8 + 2 * t;
            if (accum) {
                if (v0) { atomicAdd(o0 + c, ac[mt][nt][0]); atomicAdd(o0 + c + 1, ac[mt][nt][1]); }
                if (v1) { atomicAdd(o1 + c, ac[mt][nt][2]); atomicAdd(o1 + c + 1, ac[mt][nt][3]); }
            } else {
                if (v0) { float2 r; r.x = ac[mt][nt][0]; r.y = ac[mt][nt][1]; *(float2*)(o0 + c) = r; }
                if (v1) { float2 r; r.x = ac[mt][nt][2]; r.y = ac[mt][nt][3]; *(float2*)(o1 + c) = r; }
            }
        }
    }
}

// ---------------- launch ----------------
extern "C" void kernel_launch(void* const* d_in, const int* in_sizes, int n_in,
                              void* d_out, int out_size)
{
    const float* x    = (const float*)d_in[0];
    const float* gw   = (const float*)d_in[1];
    const float* bias = (const float*)d_in[2];
    const float* wgu  = (const float*)d_in[3];
    const float* wdn  = (const float*)d_in[4];
    const float* sgu  = (const float*)d_in[5];
    const float* sdn  = (const float*)d_in[6];
    float* out = (float*)d_out;

    void *p_cnt, *p_tok, *p_tw, *p_t4, *p_w4, *p_act, *p_acts;
    cudaGetSymbolAddress(&p_cnt,  g_cnt);
    cudaGetSymbolAddress(&p_tok,  g_tok);
    cudaGetSymbolAddress(&p_tw,   g_tw);
    cudaGetSymbolAddress(&p_t4,   g_tid4);
    cudaGetSymbolAddress(&p_w4,   g_twk4);
    cudaGetSymbolAddress(&p_act,  g_act);
    cudaGetSymbolAddress(&p_acts, g_acts);

    cudaFuncSetAttribute(gu_mma,   cudaFuncAttributeMaxDynamicSharedMemorySize, GU_DYN);
    cudaFuncSetAttribute(down_mma, cudaFuncAttributeMaxDynamicSharedMemorySize, DN_DYN);

    // 1) router + deterministic dispatch lists
    router_kernel<<<T_TOK, 128>>>(x, gw, bias, (int*)p_t4, (float*)p_w4);
    build_lists<<<1, 16>>>((const int*)p_t4, (const float*)p_w4,
                           (int*)p_cnt, (int*)p_tok, (float*)p_tw);

    // 2) gate_up + silu (tensor cores via mma.sync tf32)
    gu_mma<<<dim3(SI / 128, T_TOK / 128, 1), 256, GU_DYN>>>(
        x, sgu, (float*)p_acts, nullptr, nullptr, nullptr, SI, HDIM);
    gu_mma<<<dim3(IDIM / 128, T_TOK / 128, NEXP), 256, GU_DYN>>>(
        x, wgu, (float*)p_act, (const int*)p_tok, (const float*)p_tw,
        (const int*)p_cnt, IDIM, HDIM);

    // 3) down-proj: shared writes out (init), routed accumulates
    down_mma<<<dim3(HDIM / 256, T_TOK / 128, 1), 256, DN_DYN>>>(
        (const float*)p_acts, sdn, out, nullptr, nullptr, SI, 0);
    down_mma<<<dim3(HDIM / 256, T_TOK / 128, NEXP), 256, DN_DYN>>>(
        (const float*)p_act, wdn, out, (const int*)p_tok,
        (const int*)p_cnt, IDIM, 1);
}

// round 9
// speedup vs baseline: 2.3610x; 2.3610x over previous
#include <cuda_runtime.h>
#include <cuda_fp16.h>
#include <cstdint>

#define T_TOK 1024
#define HDIM  2048
#define NEXP  16
#define IDIM  1408
#define SI    2816
#define TOPK  4

typedef unsigned long long ull;
typedef unsigned int u32;

// ---------------- scratch (device globals; no allocation allowed) ----------------
__device__ int    g_cnt[NEXP];
__device__ int    g_tok[NEXP * T_TOK];
__device__ float  g_tw [NEXP * T_TOK];
__device__ int    g_tid4[T_TOK * TOPK];
__device__ float  g_twk4[T_TOK * TOPK];
__device__ __half g_act [(size_t)NEXP * T_TOK * IDIM];  // routed activations (fp16)
__device__ __half g_acts[(size_t)T_TOK * SI];           // shared activations (fp16)

// ---------------- helpers ----------------
__device__ __forceinline__ u32 h2(float lo, float hi) {
    __half2 h = __floats2half2_rn(lo, hi);
    return *reinterpret_cast<u32*>(&h);
}
// fp16 MMA m16n8k16, fp32 accumulate
__device__ __forceinline__ void mma16(float* d, const u32* a, const u32* b) {
    asm volatile(
        "mma.sync.aligned.m16n8k16.row.col.f32.f16.f16.f32 "
        "{%0,%1,%2,%3}, {%4,%5,%6,%7}, {%8,%9}, {%0,%1,%2,%3};"
        : "+f"(d[0]), "+f"(d[1]), "+f"(d[2]), "+f"(d[3])
        : "r"(a[0]), "r"(a[1]), "r"(a[2]), "r"(a[3]), "r"(b[0]), "r"(b[1]));
}
__device__ __forceinline__ float silu_f(float g) { return g / (1.f + expf(-g)); }

// ---------------- router (exact fp32) ----------------
__global__ void router_kernel(const float* __restrict__ x,
                              const float* __restrict__ gw,
                              const float* __restrict__ bias,
                              int* __restrict__ tid4, float* __restrict__ twk4)
{
    int t = blockIdx.x;
    int tid = threadIdx.x;            // 128 threads: 16 experts x 8 lanes
    int e = tid >> 3, r = tid & 7;
    const float4* x4 = reinterpret_cast<const float4*>(x + (size_t)t * HDIM);
    const float4* w4 = reinterpret_cast<const float4*>(gw + (size_t)e * HDIM);
    float s = 0.f;
    #pragma unroll 4
    for (int j = r; j < HDIM / 4; j += 8) {
        float4 a = x4[j], b = w4[j];
        s += a.x * b.x + a.y * b.y + a.z * b.z + a.w * b.w;
    }
    #pragma unroll
    for (int o = 4; o > 0; o >>= 1) s += __shfl_down_sync(0xffffffffu, s, o, 8);
    __shared__ float logit[NEXP];
    if (r == 0) logit[e] = s;
    __syncthreads();
    if (tid == 0) {
        float sc[NEXP], sb[NEXP];
        #pragma unroll
        for (int i = 0; i < NEXP; i++) {
            sc[i] = 1.f / (1.f + expf(-logit[i]));
            sb[i] = sc[i] + bias[i];
        }
        float gsc[4];
        #pragma unroll
        for (int g = 0; g < 4; g++) {
            const float* p = sb + g * 4;
            float m1 = p[0]; int i1 = 0;
            for (int i = 1; i < 4; i++) if (p[i] > m1) { m1 = p[i]; i1 = i; }
            float m2 = -1e30f;
            for (int i = 0; i < 4; i++) if (i != i1 && p[i] > m2) m2 = p[i];
            gsc[g] = m1 + m2;
        }
        int g1 = 0; for (int g = 1; g < 4; g++) if (gsc[g] > gsc[g1]) g1 = g;
        int g2 = (g1 == 0) ? 1 : 0;
        for (int g = 0; g < 4; g++) if (g != g1 && gsc[g] > gsc[g2]) g2 = g;
        bool allow[NEXP];
        for (int i = 0; i < NEXP; i++) { int g = i >> 2; allow[i] = (g == g1 || g == g2); }
        int ids[TOPK]; float wsum = 0.f;
        for (int k = 0; k < TOPK; k++) {
            int best = 0; float bv = -1e30f;
            for (int i = 0; i < NEXP; i++)
                if (allow[i] && sb[i] > bv) { bv = sb[i]; best = i; }
            allow[best] = false;
            ids[k] = best;
            wsum += sc[best];
        }
        for (int k = 0; k < TOPK; k++) {
            tid4[t * TOPK + k] = ids[k];
            twk4[t * TOPK + k] = sc[ids[k]] / wsum;
        }
    }
}

// ---------------- deterministic per-expert token lists ----------------
__global__ void build_lists(const int* __restrict__ tid4, const float* __restrict__ twk4,
                            int* __restrict__ cnt, int* __restrict__ tok, float* __restrict__ tw)
{
    int e = threadIdx.x;
    if (e >= NEXP) return;
    int c = 0;
    for (int t = 0; t < T_TOK; t++) {
        int4  id = reinterpret_cast<const int4*>(tid4)[t];
        float4 w = reinterpret_cast<const float4*>(twk4)[t];
        if (id.x == e) { tok[e * T_TOK + c] = t; tw[e * T_TOK + c] = w.x * 2.5f; c++; }
        if (id.y == e) { tok[e * T_TOK + c] = t; tw[e * T_TOK + c] = w.y * 2.5f; c++; }
        if (id.z == e) { tok[e * T_TOK + c] = t; tw[e * T_TOK + c] = w.z * 2.5f; c++; }
        if (id.w == e) { tok[e * T_TOK + c] = t; tw[e * T_TOK + c] = w.w * 2.5f; c++; }
    }
    cnt[e] = c;
}

// =====================================================================
// gate_up GEMM via mma.sync fp16 (m16n8k16): CTA tile 128m x (128g+128u)
// 8 warps = 2m x 4n; warp tile 64m x (32g + 32u). act = silu(g)*u*w (fp16 out)
// SMEM stores k-PAIRS as half2 words:
//   As[row][word]  word = (A[row][2k], A[row][2k+1]),  stride SAW=20 words
//   Bp[k2][n]      word = (B[2k2][n], B[2k2+1][n]),    stride SBW=136 words
// =====================================================================
#define SAW 20
#define SBW 136
__global__ void __launch_bounds__(256)
gu_mma(const float* __restrict__ X, const float* __restrict__ W,
       __half* __restrict__ ACT,
       const int* __restrict__ tok, const float* __restrict__ tw,
       const int* __restrict__ cnt, int Iw, int K)
{
    __shared__ u32 As[128 * SAW];
    __shared__ u32 Bg[16 * SBW];
    __shared__ u32 Bu[16 * SBW];
    __shared__ int   tokSm[128];
    __shared__ float twSm[128];

    int e = blockIdx.z;
    int cn = cnt ? cnt[e] : T_TOK;
    int m0 = blockIdx.y * 128;
    if (m0 >= cn) return;
    int n0 = blockIdx.x * 128;
    int ldW = 2 * Iw;
    const float* We = W + (size_t)e * K * ldW;
    __half* actE = ACT + (size_t)e * T_TOK * Iw;

    int tid = threadIdx.x;
    if (tid < 128) {
        int s = m0 + tid; int a; float wv;
        if (tok) {
            const int* tokE = tok + e * T_TOK;
            const float* twE = tw + e * T_TOK;
            if (s < cn) { a = tokE[s]; wv = twE[s]; } else { a = 0; wv = 0.f; }
        } else { a = s; wv = 1.f; }
        tokSm[tid] = a; twSm[tid] = wv;
    }
    __syncthreads();

    // staging mapping
    int arow = tid >> 1, kw = (tid & 1) * 8;           // A: word offset within row
    const float* aP = X + (size_t)tokSm[arow] * K + kw * 2;
    int bk2 = tid >> 4, bn = (tid & 15) * 4;            // B: k2-row + n-word base (chunks +64)
    const float* gP0 = We + (size_t)(2 * bk2) * ldW + n0 + bn;
    const float* gP1 = gP0 + ldW;
    const float* uP0 = gP0 + Iw;
    const float* uP1 = gP1 + Iw;

    // warp mapping: 2m x 4n
    int w = tid >> 5, lane = tid & 31;
    int g = lane >> 2, t = lane & 3;
    int wm = (w & 1) * 64, wn = (w >> 1) * 32;

    float ag[4][4][4], au[4][4][4];
    #pragma unroll
    for (int i = 0; i < 4; i++)
        #pragma unroll
        for (int j = 0; j < 4; j++)
            #pragma unroll
            for (int q = 0; q < 4; q++) { ag[i][j][q] = 0.f; au[i][j][q] = 0.f; }

    float4 pa[4];           // A: 16 floats
    float4 pg0[2], pg1[2];  // Bg rows 2bk2 / 2bk2+1, chunks n = bn, bn+64
    float4 pu0[2], pu1[2];
    #pragma unroll
    for (int i = 0; i < 4; i++) pa[i] = *(const float4*)(aP + 4 * i);
    #pragma unroll
    for (int i = 0; i < 2; i++) {
        pg0[i] = *(const float4*)(gP0 + 64 * i);
        pg1[i] = *(const float4*)(gP1 + 64 * i);
        pu0[i] = *(const float4*)(uP0 + 64 * i);
        pu1[i] = *(const float4*)(uP1 + 64 * i);
    }

    const int NK = K / 32;
    for (int it = 0; it < NK; ++it) {
        // stage current tile (convert fp32 -> packed half2 pairs)
        {
            uint4 w0, w1;
            w0.x = h2(pa[0].x, pa[0].y); w0.y = h2(pa[0].z, pa[0].w);
            w0.z = h2(pa[1].x, pa[1].y); w0.w = h2(pa[1].z, pa[1].w);
            w1.x = h2(pa[2].x, pa[2].y); w1.y = h2(pa[2].z, pa[2].w);
            w1.z = h2(pa[3].x, pa[3].y); w1.w = h2(pa[3].z, pa[3].w);
            *(uint4*)&As[arow * SAW + kw]     = w0;
            *(uint4*)&As[arow * SAW + kw + 4] = w1;
            #pragma unroll
            for (int i = 0; i < 2; i++) {
                uint4 bg, bu;
                bg.x = h2(pg0[i].x, pg1[i].x); bg.y = h2(pg0[i].y, pg1[i].y);
                bg.z = h2(pg0[i].z, pg1[i].z); bg.w = h2(pg0[i].w, pg1[i].w);
                bu.x = h2(pu0[i].x, pu1[i].x); bu.y = h2(pu0[i].y, pu1[i].y);
                bu.z = h2(pu0[i].z, pu1[i].z); bu.w = h2(pu0[i].w, pu1[i].w);
                *(uint4*)&Bg[bk2 * SBW + bn + 64 * i] = bg;
                *(uint4*)&Bu[bk2 * SBW + bn + 64 * i] = bu;
            }
        }
        __syncthreads();

        // prefetch next tile into registers
        if (it + 1 < NK) {
            const float* aN  = aP + (it + 1) * 32;
            const float* gN0 = gP0 + (size_t)(it + 1) * 32 * ldW;
            const float* gN1 = gN0 + ldW;
            const float* uN0 = gN0 + Iw;
            const float* uN1 = gN1 + Iw;
            #pragma unroll
            for (int i = 0; i < 4; i++) pa[i] = *(const float4*)(aN + 4 * i);
            #pragma unroll
            for (int i = 0; i < 2; i++) {
                pg0[i] = *(const float4*)(gN0 + 64 * i);
                pg1[i] = *(const float4*)(gN1 + 64 * i);
                pu0[i] = *(const float4*)(uN0 + 64 * i);
                pu1[i] = *(const float4*)(uN1 + 64 * i);
            }
        }

        // MMA: 2 k16-steps per 32-k tile
        #pragma unroll
        for (int ks = 0; ks < 2; ++ks) {
            int k0 = ks * 8;
            u32 af[4][4];
            #pragma unroll
            for (int mt = 0; mt < 4; ++mt) {
                int r = wm + mt * 16 + g;
                af[mt][0] = As[r * SAW + k0 + t];
                af[mt][1] = As[(r + 8) * SAW + k0 + t];
                af[mt][2] = As[r * SAW + k0 + t + 4];
                af[mt][3] = As[(r + 8) * SAW + k0 + t + 4];
            }
            #pragma unroll
            for (int nt = 0; nt < 4; ++nt) {
                int n = wn + nt * 8 + g;
                u32 bg2[2] = { Bg[(k0 + t) * SBW + n], Bg[(k0 + t + 4) * SBW + n] };
                u32 bu2[2] = { Bu[(k0 + t) * SBW + n], Bu[(k0 + t + 4) * SBW + n] };
                #pragma unroll
                for (int mt = 0; mt < 4; ++mt) {
                    mma16(ag[mt][nt], af[mt], bg2);
                    mma16(au[mt][nt], af[mt], bu2);
                }
            }
        }
        __syncthreads();
    }

    // epilogue: silu(g)*u*w -> act (fp16)
    #pragma unroll
    for (int mt = 0; mt < 4; ++mt) {
        int l0 = wm + mt * 16 + g;
        int s0 = m0 + l0, s1 = s0 + 8;
        bool v0 = s0 < cn, v1 = s1 < cn;
        float w0 = twSm[l0], w1 = twSm[l0 + 8];
        __half* o0 = actE + (size_t)s0 * Iw + n0 + wn;
        __half* o1 = actE + (size_t)s1 * Iw + n0 + wn;
        #pragma unroll
        for (int nt = 0; nt < 4; ++nt) {
            int c = nt * 8 + 2 * t;
            if (v0) {
                *(u32*)(o0 + c) = h2(silu_f(ag[mt][nt][0]) * au[mt][nt][0] * w0,
                                     silu_f(ag[mt][nt][1]) * au[mt][nt][1] * w0);
            }
            if (v1) {
                *(u32*)(o1 + c) = h2(silu_f(ag[mt][nt][2]) * au[mt][nt][2] * w1,
                                     silu_f(ag[mt][nt][3]) * au[mt][nt][3] * w1);
            }
        }
    }
}

// =====================================================================
// down-proj GEMM via mma.sync fp16: CTA tile 128m x 256n
// 8 warps = 2m x 4n; warp tile 64m x 64n. A (act) already fp16 pair-packed.
// routed: atomicAdd scatter to out rows; shared: plain store.
// =====================================================================
#define SBWD 264
__global__ void __launch_bounds__(256)
down_mma(const __half* __restrict__ A, const float* __restrict__ W,
         float* __restrict__ OUT, const int* __restrict__ tok,
         const int* __restrict__ cnt, int K, int accum)
{
    __shared__ u32 As[128 * SAW];
    __shared__ u32 Bs[16 * SBWD];
    __shared__ int tokSm[128];

    int e = blockIdx.z;
    int cn = cnt ? cnt[e] : T_TOK;
    int m0 = blockIdx.y * 128;
    if (m0 >= cn) return;
    int n0 = blockIdx.x * 256;
    const __half* Ae = A + (size_t)e * T_TOK * K;
    const float* Be = W + (size_t)e * K * HDIM;

    int tid = threadIdx.x;
    if (tid < 128) {
        int s = m0 + tid;
        tokSm[tid] = tok ? ((s < cn) ? tok[e * T_TOK + s] : 0) : s;
    }
    __syncthreads();

    int arow = tid >> 1, kw = (tid & 1) * 8;
    const __half* aP = Ae + (size_t)(m0 + arow) * K + kw * 2;
    int bk2 = tid >> 4, bn = (tid & 15) * 4;
    const float* bP0 = Be + (size_t)(2 * bk2) * HDIM + n0 + bn;
    const float* bP1 = bP0 + HDIM;

    int w = tid >> 5, lane = tid & 31;
    int g = lane >> 2, t = lane & 3;
    int wm = (w & 1) * 64, wn = (w >> 1) * 64;

    float ac[4][8][4];
    #pragma unroll
    for (int i = 0; i < 4; i++)
        #pragma unroll
        for (int j = 0; j < 8; j++)
            #pragma unroll
            for (int q = 0; q < 4; q++) ac[i][j][q] = 0.f;

    uint4 pa[2];            // A: 16 halves (already k-pair packed)
    float4 pb0[4], pb1[4];  // B rows 2bk2/2bk2+1, chunks n = bn + 64i
    #pragma unroll
    for (int i = 0; i < 2; i++) pa[i] = *(const uint4*)(aP + 8 * i);
    #pragma unroll
    for (int i = 0; i < 4; i++) {
        pb0[i] = *(const float4*)(bP0 + 64 * i);
        pb1[i] = *(const float4*)(bP1 + 64 * i);
    }

    const int NK = K / 32;
    for (int it = 0; it < NK; ++it) {
        {
            *(uint4*)&As[arow * SAW + kw]     = pa[0];
            *(uint4*)&As[arow * SAW + kw + 4] = pa[1];
            #pragma unroll
            for (int i = 0; i < 4; i++) {
                uint4 bb;
                bb.x = h2(pb0[i].x, pb1[i].x); bb.y = h2(pb0[i].y, pb1[i].y);
                bb.z = h2(pb0[i].z, pb1[i].z); bb.w = h2(pb0[i].w, pb1[i].w);
                *(uint4*)&Bs[bk2 * SBWD + bn + 64 * i] = bb;
            }
        }
        __syncthreads();

        if (it + 1 < NK) {
            const __half* aN = aP + (it + 1) * 32;
            const float* bN0 = bP0 + (size_t)(it + 1) * 32 * HDIM;
            const float* bN1 = bN0 + HDIM;
            #pragma unroll
            for (int i = 0; i < 2; i++) pa[i] = *(const uint4*)(aN + 8 * i);
            #pragma unroll
            for (int i = 0; i < 4; i++) {
                pb0[i] = *(const float4*)(bN0 + 64 * i);
                pb1[i] = *(const float4*)(bN1 + 64 * i);
            }
        }

        #pragma unroll
        for (int ks = 0; ks < 2; ++ks) {
            int k0 = ks * 8;
            u32 af[4][4];
            #pragma unroll
            for (int mt = 0; mt < 4; ++mt) {
                int r = wm + mt * 16 + g;
                af[mt][0] = As[r * SAW + k0 + t];
                af[mt][1] = As[(r + 8) * SAW + k0 + t];
                af[mt][2] = As[r * SAW + k0 + t + 4];
                af[mt][3] = As[(r + 8) * SAW + k0 + t + 4];
            }
            #pragma unroll
            for (int nt = 0; nt < 8; ++nt) {
                int n = wn + nt * 8 + g;
                u32 bf2[2] = { Bs[(k0 + t) * SBWD + n], Bs[(k0 + t + 4) * SBWD + n] };
                #pragma unroll
                for (int mt = 0; mt < 4; ++mt)
                    mma16(ac[mt][nt], af[mt], bf2);
            }
        }
        __syncthreads();
    }

    #pragma unroll
    for (int mt = 0; mt < 4; ++mt) {
        int l0 = wm + mt * 16 + g;
        int s0 = m0 + l0, s1 = s0 + 8;
        bool v0 = s0 < cn, v1 = s1 < cn;
        float* o0 = OUT + (size_t)tokSm[l0] * HDIM + n0 + wn;
        float* o1 = OUT + (size_t)tokSm[l0 + 8] * HDIM + n0 + wn;
        #pragma unroll
        for (int nt = 0; nt < 8; ++nt) {
            int c = nt * 8 + 2 * t;
            if (accum) {
                if (v0) { atomicAdd(o0 + c, ac[mt][nt][0]); atomicAdd(o0 + c + 1, ac[mt][nt][1]); }
                if (v1) { atomicAdd(o1 + c, ac[mt][nt][2]); atomicAdd(o1 + c + 1, ac[mt][nt][3]); }
            } else {
                if (v0) { float2 r; r.x = ac[mt][nt][0]; r.y = ac[mt][nt][1]; *(float2*)(o0 + c) = r; }
                if (v1) { float2 r; r.x = ac[mt][nt][2]; r.y = ac[mt][nt][3]; *(float2*)(o1 + c) = r; }
            }
        }
    }
}

// ---------------- launch ----------------
extern "C" void kernel_launch(void* const* d_in, const int* in_sizes, int n_in,
                              void* d_out, int out_size)
{
    const float* x    = (const float*)d_in[0];
    const float* gw   = (const float*)d_in[1];
    const float* bias = (const float*)d_in[2];
    const float* wgu  = (const float*)d_in[3];
    const float* wdn  = (const float*)d_in[4];
    const float* sgu  = (const float*)d_in[5];
    const float* sdn  = (const float*)d_in[6];
    float* out = (float*)d_out;

    void *p_cnt, *p_tok, *p_tw, *p_t4, *p_w4, *p_act, *p_acts;
    cudaGetSymbolAddress(&p_cnt,  g_cnt);
    cudaGetSymbolAddress(&p_tok,  g_tok);
    cudaGetSymbolAddress(&p_tw,   g_tw);
    cudaGetSymbolAddress(&p_t4,   g_tid4);
    cudaGetSymbolAddress(&p_w4,   g_twk4);
    cudaGetSymbolAddress(&p_act,  g_act);
    cudaGetSymbolAddress(&p_acts, g_acts);

    // 1) router + deterministic dispatch lists
    router_kernel<<<T_TOK, 128>>>(x, gw, bias, (int*)p_t4, (float*)p_w4);
    build_lists<<<1, 16>>>((const int*)p_t4, (const float*)p_w4,
                           (int*)p_cnt, (int*)p_tok, (float*)p_tw);

    // 2) gate_up + silu (fp16 tensor cores)
    gu_mma<<<dim3(SI / 128, T_TOK / 128, 1), 256>>>(
        x, sgu, (__half*)p_acts, nullptr, nullptr, nullptr, SI, HDIM);
    gu_mma<<<dim3(IDIM / 128, T_TOK / 128, NEXP), 256>>>(
        x, wgu, (__half*)p_act, (const int*)p_tok, (const float*)p_tw,
        (const int*)p_cnt, IDIM, HDIM);

    // 3) down-proj: shared writes out (init), routed accumulates
    down_mma<<<dim3(HDIM / 256, T_TOK / 128, 1), 256>>>(
        (const __half*)p_acts, sdn, out, nullptr, nullptr, SI, 0);
    down_mma<<<dim3(HDIM / 256, T_TOK / 128, NEXP), 256>>>(
        (const __half*)p_act, wdn, out, (const int*)p_tok,
        (const int*)p_cnt, IDIM, 1);
}